// round 1
// baseline (speedup 1.0000x reference)
#include <cuda_runtime.h>
#include <math.h>

#define BB 8
#define CC 256
#define NN 2304   // 48*48

// Scratch (cudaMalloc is banned -> __device__ globals).
// branch 0: Q/K from y-projections (attn2), V = v1 (from x)  -> out1
// branch 1: Q/K from x-projections (attn1), V = v2 (from y)  -> out2
__device__ float g_q[2][BB][NN][32];
__device__ float g_k[2][BB][NN][32];
__device__ float g_v[2][BB][NN][CC];

// ---------------------------------------------------------------------------
// Projection GEMM: out[b][n][o] = sum_c W[o][c] * in[b][c][n] + bias[o]
// O space = [q(32) | k(32) | v(256)] = 320 outputs, selected by blockIdx.y.
// Tile: 64 n x 32 o, K-chunk 32. 256 threads, 8 outputs each (2o x 4n).
// ---------------------------------------------------------------------------
__global__ __launch_bounds__(256) void proj_kernel(
    const float* __restrict__ in,
    const float* __restrict__ wq, const float* __restrict__ bq,
    const float* __restrict__ wk, const float* __restrict__ bk,
    const float* __restrict__ wv, const float* __restrict__ bv,
    int qb, int kb, int vb)
{
    const int b  = blockIdx.z;
    const int n0 = blockIdx.x * 64;
    const int o0 = blockIdx.y * 32;

    __shared__ float sW[32][33];   // [o][c]
    __shared__ float sX[32][68];   // [c][n], pad 68 (row byte stride 272 = 17*16, f4-aligned)

    const int tid = threadIdx.x;
    const int ox  = tid & 15;      // o lane (handles ox and ox+16)
    const int ny  = tid >> 4;      // n group (4 n's)

    float acc[2][4] = {};
    const float* inb = in + (size_t)b * CC * NN;

    for (int k0 = 0; k0 < CC; k0 += 32) {
        // W tile: 32 rows x 32 c
        {
            int row = tid >> 3;
            int c4  = (tid & 7) << 2;
            int o   = o0 + row;
            const float* wrow = (o < 32) ? (wq + (size_t)o * CC)
                              : (o < 64) ? (wk + (size_t)(o - 32) * CC)
                                         : (wv + (size_t)(o - 64) * CC);
            float4 w4 = *(const float4*)(wrow + k0 + c4);
            sW[row][c4+0] = w4.x; sW[row][c4+1] = w4.y;
            sW[row][c4+2] = w4.z; sW[row][c4+3] = w4.w;
        }
        // X tile: 32 c-rows x 64 n
        {
            int r  = tid >> 4;
            int c4 = (tid & 15) << 2;
            float4 a0 = *(const float4*)(inb + (size_t)(k0 + r)      * NN + n0 + c4);
            float4 a1 = *(const float4*)(inb + (size_t)(k0 + r + 16) * NN + n0 + c4);
            *(float4*)&sX[r][c4]      = a0;
            *(float4*)&sX[r + 16][c4] = a1;
        }
        __syncthreads();

        #pragma unroll
        for (int cc = 0; cc < 32; cc++) {
            float w0 = sW[ox][cc];
            float w1 = sW[ox + 16][cc];
            float4 xv = *(const float4*)&sX[cc][ny << 2];
            acc[0][0] += w0 * xv.x; acc[0][1] += w0 * xv.y;
            acc[0][2] += w0 * xv.z; acc[0][3] += w0 * xv.w;
            acc[1][0] += w1 * xv.x; acc[1][1] += w1 * xv.y;
            acc[1][2] += w1 * xv.z; acc[1][3] += w1 * xv.w;
        }
        __syncthreads();
    }

    // Epilogue: bias + scatter to destination buffer
    #pragma unroll
    for (int half = 0; half < 2; half++) {
        int o = o0 + ox + half * 16;
        float bias;
        float* dstp;
        int od;
        if (o < 32)      { bias = bq[o];      dstp = &g_q[qb][b][0][o];       od = 32; }
        else if (o < 64) { bias = bk[o - 32]; dstp = &g_k[kb][b][0][o - 32];  od = 32; }
        else             { bias = bv[o - 64]; dstp = &g_v[vb][b][0][o - 64];  od = CC; }
        #pragma unroll
        for (int i = 0; i < 4; i++) {
            int n = n0 + (ny << 2) + i;
            dstp[(size_t)n * od] = acc[half][i] + bias;
        }
    }
}

// ---------------------------------------------------------------------------
// Fused flash attention + residual:
//   out[b][c][i] = gamma * ( sum_j softmax_j(q_i . k_j) * v[c][j] ) + res[b][c][i]
// Block: 64 queries, streams 32-j tiles. 256 threads.
// Acc mapping: cg = tid&15 owns float4 channel groups {cg, cg+16, cg+32, cg+48};
//              qslot = tid>>4 owns queries {qslot, qslot+16, qslot+32, qslot+48}.
// ---------------------------------------------------------------------------
__global__ __launch_bounds__(256, 2) void attn_kernel(
    int br, const float* __restrict__ res, const float* __restrict__ gamma,
    float* __restrict__ out)
{
    const int b  = blockIdx.y;
    const int i0 = blockIdx.x * 64;
    const int tid = threadIdx.x;

    extern __shared__ float smem[];
    float*  sQ = smem;                    // [64][36]  (pad: row 144B, f4-aligned)
    float*  sK = sQ + 64 * 36;            // [32][36]
    float4* sV = (float4*)(sK + 32 * 36); // [32][64]  (v[j][c] as float4, 13824B offset ok)
    float*  sP = (float*)(sV + 32 * 64);  // [32][64]  layout [j][q]
    float*  sScale = sP + 32 * 64;        // [64]
    float*  sL     = sScale + 64;         // [64]

    const float* qg = &g_q[br][b][0][0];
    const float* kg = &g_k[br][b][0][0];
    const float* vg = &g_v[br][b][0][0];

    // Load Q tile (persistent for whole block)
    #pragma unroll
    for (int r = 0; r < 2; r++) {
        int idx = tid + r * 256;          // 0..511
        int row = idx >> 3;
        int c4  = (idx & 7) << 2;
        float4 v4 = *(const float4*)(qg + (size_t)(i0 + row) * 32 + c4);
        *(float4*)&sQ[row * 36 + c4] = v4;
    }

    const int sq    = tid >> 2;           // S-phase query 0..63
    const int sj0   = tid & 3;            // S-phase j offset
    const int cg    = tid & 15;
    const int qslot = tid >> 4;

    float m_run = -1e30f, l_run = 0.f;    // live only in threads < 64
    float4 acc[4][4];
    #pragma unroll
    for (int qi = 0; qi < 4; qi++)
        #pragma unroll
        for (int k4 = 0; k4 < 4; k4++)
            acc[qi][k4] = make_float4(0.f, 0.f, 0.f, 0.f);

    for (int jt = 0; jt < NN / 32; jt++) {
        const int j0 = jt * 32;
        // K tile: 32x32
        {
            int row = tid >> 3;
            int c4  = (tid & 7) << 2;
            float4 v4 = *(const float4*)(kg + (size_t)(j0 + row) * 32 + c4);
            *(float4*)&sK[row * 36 + c4] = v4;
        }
        // V tile: 32 x 256 (2048 float4)
        #pragma unroll
        for (int r = 0; r < 8; r++) {
            int idx = tid + r * 256;
            int row = idx >> 6;
            int c4i = idx & 63;
            sV[row * 64 + c4i] = *(const float4*)(vg + (size_t)(j0 + row) * CC + (c4i << 2));
        }
        __syncthreads();

        // S = Q.K^T for this tile (each thread: 8 dots)
        #pragma unroll
        for (int s = 0; s < 8; s++) {
            int j = sj0 + (s << 2);
            float d = 0.f;
            #pragma unroll
            for (int c4 = 0; c4 < 8; c4++) {
                float4 qv = *(const float4*)&sQ[sq * 36 + (c4 << 2)];
                float4 kv = *(const float4*)&sK[j  * 36 + (c4 << 2)];
                d += qv.x * kv.x + qv.y * kv.y + qv.z * kv.z + qv.w * kv.w;
            }
            sP[j * 64 + sq] = d;
        }
        __syncthreads();

        // Online softmax update (threads 0..63, one query each)
        if (tid < 64) {
            float mx = m_run;
            #pragma unroll
            for (int j = 0; j < 32; j++) mx = fmaxf(mx, sP[j * 64 + tid]);
            float scale = __expf(m_run - mx);
            float ls = l_run * scale;
            #pragma unroll
            for (int j = 0; j < 32; j++) {
                float p = __expf(sP[j * 64 + tid] - mx);
                sP[j * 64 + tid] = p;
                ls += p;
            }
            m_run = mx;
            l_run = ls;
            sScale[tid] = scale;
        }
        __syncthreads();

        // Rescale accumulators, then acc += P * V
        #pragma unroll
        for (int qi = 0; qi < 4; qi++) {
            float scq = sScale[qslot + (qi << 4)];
            #pragma unroll
            for (int k4 = 0; k4 < 4; k4++) {
                acc[qi][k4].x *= scq; acc[qi][k4].y *= scq;
                acc[qi][k4].z *= scq; acc[qi][k4].w *= scq;
            }
        }
        #pragma unroll 4
        for (int j = 0; j < 32; j++) {
            float4 v0 = sV[j * 64 + cg];
            float4 v1 = sV[j * 64 + cg + 16];
            float4 v2 = sV[j * 64 + cg + 32];
            float4 v3 = sV[j * 64 + cg + 48];
            #pragma unroll
            for (int qi = 0; qi < 4; qi++) {
                float p = sP[j * 64 + qslot + (qi << 4)];
                acc[qi][0].x += p * v0.x; acc[qi][0].y += p * v0.y;
                acc[qi][0].z += p * v0.z; acc[qi][0].w += p * v0.w;
                acc[qi][1].x += p * v1.x; acc[qi][1].y += p * v1.y;
                acc[qi][1].z += p * v1.z; acc[qi][1].w += p * v1.w;
                acc[qi][2].x += p * v2.x; acc[qi][2].y += p * v2.y;
                acc[qi][2].z += p * v2.z; acc[qi][2].w += p * v2.w;
                acc[qi][3].x += p * v3.x; acc[qi][3].y += p * v3.y;
                acc[qi][3].z += p * v3.z; acc[qi][3].w += p * v3.w;
            }
        }
        __syncthreads();
    }

    if (tid < 64) sL[tid] = l_run;
    __syncthreads();

    const float g = gamma[0];
    #pragma unroll
    for (int qi = 0; qi < 4; qi++) {
        int q = qslot + (qi << 4);
        int i = i0 + q;
        float rl = g / sL[q];
        #pragma unroll
        for (int k4 = 0; k4 < 4; k4++) {
            int c4    = cg + (k4 << 4);
            int cbase = c4 << 2;
            size_t base = ((size_t)b * CC + cbase) * NN + i;
            out[base]          = acc[qi][k4].x * rl + res[base];
            out[base +     NN] = acc[qi][k4].y * rl + res[base +     NN];
            out[base + 2 * NN] = acc[qi][k4].z * rl + res[base + 2 * NN];
            out[base + 3 * NN] = acc[qi][k4].w * rl + res[base + 3 * NN];
        }
    }
}

// ---------------------------------------------------------------------------

extern "C" void kernel_launch(void* const* d_in, const int* in_sizes, int n_in,
                              void* d_out, int out_size)
{
    const float* x   = (const float*)d_in[0];
    const float* y   = (const float*)d_in[1];
    const float* wqx = (const float*)d_in[2];
    const float* bqx = (const float*)d_in[3];
    const float* wkx = (const float*)d_in[4];
    const float* bkx = (const float*)d_in[5];
    const float* wvx = (const float*)d_in[6];
    const float* bvx = (const float*)d_in[7];
    const float* wqy = (const float*)d_in[8];
    const float* bqy = (const float*)d_in[9];
    const float* wky = (const float*)d_in[10];
    const float* bky = (const float*)d_in[11];
    const float* wvy = (const float*)d_in[12];
    const float* bvy = (const float*)d_in[13];
    const float* gx  = (const float*)d_in[14];
    const float* gy  = (const float*)d_in[15];
    float* out = (float*)d_out;

    const int ATTN_SMEM = (64*36 + 32*36 + 32*64*4 + 32*64 + 128) * (int)sizeof(float);
    cudaFuncSetAttribute(attn_kernel, cudaFuncAttributeMaxDynamicSharedMemorySize, ATTN_SMEM);

    dim3 pgrid(NN / 64, 320 / 32, BB);
    // x-projections -> q1/k1 (branch 1 Q/K), v1 (branch 0 V)
    proj_kernel<<<pgrid, 256>>>(x, wqx, bqx, wkx, bkx, wvx, bvx, 1, 1, 0);
    // y-projections -> q2/k2 (branch 0 Q/K), v2 (branch 1 V)
    proj_kernel<<<pgrid, 256>>>(y, wqy, bqy, wky, bky, wvy, bvy, 0, 0, 1);

    dim3 agrid(NN / 64, BB);
    // out1 = gamma_x * (v1 routed by attn2) + x
    attn_kernel<<<agrid, 256, ATTN_SMEM>>>(0, x, gx, out);
    // out2 = gamma_y * (v2 routed by attn1) + y
    attn_kernel<<<agrid, 256, ATTN_SMEM>>>(1, y, gy, out + (size_t)BB * CC * NN);
}

// round 3
// speedup vs baseline: 1.0386x; 1.0386x over previous
#include <cuda_runtime.h>
#include <math.h>

#define BB 8
#define CC 256
#define NN 2304   // 48*48

typedef unsigned long long u64;

__device__ __forceinline__ u64 pack2(float lo, float hi) {
    u64 r; asm("mov.b64 %0,{%1,%2};" : "=l"(r) : "f"(lo), "f"(hi)); return r;
}
__device__ __forceinline__ float2 unpack2(u64 v) {
    float2 f; asm("mov.b64 {%0,%1},%2;" : "=f"(f.x), "=f"(f.y) : "l"(v)); return f;
}
__device__ __forceinline__ u64 ffma2(u64 a, u64 b, u64 c) {
    u64 d; asm("fma.rn.f32x2 %0,%1,%2,%3;" : "=l"(d) : "l"(a), "l"(b), "l"(c)); return d;
}

// Scratch (cudaMalloc is banned -> __device__ globals).
// branch 0: Q/K from y-projections (attn2), V = v1 (from x)  -> out1
// branch 1: Q/K from x-projections (attn1), V = v2 (from y)  -> out2
__device__ float g_q[2][BB][NN][32];
__device__ float g_k[2][BB][NN][32];
__device__ float g_v[2][BB][NN][CC];

// ---------------------------------------------------------------------------
// Projection GEMM: out[b][n][o] = sum_c W[o][c] * in[b][c][n] + bias[o]
// O space = [q(32) | k(32) | v(256)] = 320 outputs, selected by blockIdx.y.
// Inner loop uses packed fma.rn.f32x2.
// ---------------------------------------------------------------------------
__global__ __launch_bounds__(256) void proj_kernel(
    const float* __restrict__ in,
    const float* __restrict__ wq, const float* __restrict__ bq,
    const float* __restrict__ wk, const float* __restrict__ bk,
    const float* __restrict__ wv, const float* __restrict__ bv,
    int qb, int kb, int vb)
{
    const int b  = blockIdx.z;
    const int n0 = blockIdx.x * 64;
    const int o0 = blockIdx.y * 32;

    __shared__ float sW[32][33];   // [o][c]
    __shared__ float sX[32][68];   // [c][n], pad 68 (row 272B = 17*16, f4-aligned)

    const int tid = threadIdx.x;
    const int ox  = tid & 15;      // o lane (handles ox and ox+16)
    const int ny  = tid >> 4;      // n group (4 n's)

    u64 acc2[2][2] = {{0ull, 0ull}, {0ull, 0ull}};
    const float* inb = in + (size_t)b * CC * NN;

    for (int k0 = 0; k0 < CC; k0 += 32) {
        {
            int row = tid >> 3;
            int c4  = (tid & 7) << 2;
            int o   = o0 + row;
            const float* wrow = (o < 32) ? (wq + (size_t)o * CC)
                              : (o < 64) ? (wk + (size_t)(o - 32) * CC)
                                         : (wv + (size_t)(o - 64) * CC);
            float4 w4 = *(const float4*)(wrow + k0 + c4);
            sW[row][c4+0] = w4.x; sW[row][c4+1] = w4.y;
            sW[row][c4+2] = w4.z; sW[row][c4+3] = w4.w;
        }
        {
            int r  = tid >> 4;
            int c4 = (tid & 15) << 2;
            float4 a0 = *(const float4*)(inb + (size_t)(k0 + r)      * NN + n0 + c4);
            float4 a1 = *(const float4*)(inb + (size_t)(k0 + r + 16) * NN + n0 + c4);
            *(float4*)&sX[r][c4]      = a0;
            *(float4*)&sX[r + 16][c4] = a1;
        }
        __syncthreads();

        #pragma unroll
        for (int cc = 0; cc < 32; cc++) {
            float w0 = sW[ox][cc];
            float w1 = sW[ox + 16][cc];
            ulonglong2 xv = *(const ulonglong2*)&sX[cc][ny << 2];
            u64 p0 = pack2(w0, w0);
            u64 p1 = pack2(w1, w1);
            acc2[0][0] = ffma2(p0, xv.x, acc2[0][0]);
            acc2[0][1] = ffma2(p0, xv.y, acc2[0][1]);
            acc2[1][0] = ffma2(p1, xv.x, acc2[1][0]);
            acc2[1][1] = ffma2(p1, xv.y, acc2[1][1]);
        }
        __syncthreads();
    }

    #pragma unroll
    for (int half = 0; half < 2; half++) {
        int o = o0 + ox + half * 16;
        float bias;
        float* dstp;
        int od;
        if (o < 32)      { bias = bq[o];      dstp = &g_q[qb][b][0][o];       od = 32; }
        else if (o < 64) { bias = bk[o - 32]; dstp = &g_k[kb][b][0][o - 32];  od = 32; }
        else             { bias = bv[o - 64]; dstp = &g_v[vb][b][0][o - 64];  od = CC; }
        float2 v01 = unpack2(acc2[half][0]);
        float2 v23 = unpack2(acc2[half][1]);
        float vals[4] = {v01.x, v01.y, v23.x, v23.y};
        #pragma unroll
        for (int i = 0; i < 4; i++) {
            int n = n0 + (ny << 2) + i;
            dstp[(size_t)n * od] = vals[i] + bias;
        }
    }
}

// ---------------------------------------------------------------------------
// Fused attention (no max-subtraction softmax; logits are O(34) so exp is safe
// in fp32) + residual. Block: 64 queries, 256 threads = 8 warps.
// Warp w owns queries w*8..w*8+7. Lane l owns channel float4 groups l and l+32.
// p values live in registers of the warp that computed them; PV fetches via shfl.
// All FMAs are packed fma.rn.f32x2.
// ---------------------------------------------------------------------------
__global__ __launch_bounds__(256, 2) void attn_kernel(
    int br, const float* __restrict__ res, const float* __restrict__ gamma,
    float* __restrict__ out)
{
    const int b   = blockIdx.y;
    const int i0  = blockIdx.x * 64;
    const int tid = threadIdx.x;
    const int w   = tid >> 5;
    const int l   = tid & 31;
    const int qloc = l & 7;        // this lane's S-phase query (within warp's 8)
    const int jg   = l >> 3;       // this lane's S-phase j offset group

    __shared__ float  sK[32 * 36];       // [j][c] pad 36 (row 144B, 16B-aligned)
    __shared__ float4 sV[32 * 64];       // [j][c4]

    const float* kg = &g_k[br][b][0][0];
    const float* vg = &g_v[br][b][0][0];

    // Cache this lane's Q row (query i0 + w*8 + qloc) in registers as f32x2.
    // qreg[2*i]   = channels 4i, 4i+1
    // qreg[2*i+1] = channels 4i+2, 4i+3
    u64 qreg[16];
    {
        const ulonglong2* qp = (const ulonglong2*)&g_q[br][b][i0 + w * 8 + qloc][0];
        #pragma unroll
        for (int i = 0; i < 8; i++) {
            ulonglong2 qv = qp[i];
            qreg[2 * i]     = qv.x;
            qreg[2 * i + 1] = qv.y;
        }
    }

    u64 acc[8][4];                 // [q][ (c4=l).xy, .zw, (c4=l+32).xy, .zw ]
    #pragma unroll
    for (int q = 0; q < 8; q++)
        #pragma unroll
        for (int k = 0; k < 4; k++) acc[q][k] = 0ull;
    float lsum = 0.f;

    for (int jt = 0; jt < NN / 32; jt++) {
        const int j0 = jt * 32;
        __syncthreads();           // previous tile's PV reads complete
        // Stage K (32x32) and V (32x256) tiles
        {
            int r = tid >> 3, c4 = (tid & 7) << 2;
            *(float4*)&sK[r * 36 + c4] = *(const float4*)(kg + (size_t)(j0 + r) * 32 + c4);
            #pragma unroll
            for (int i = 0; i < 8; i++) {
                int idx = tid + i * 256;
                int row = idx >> 6, cc = idx & 63;
                sV[row * 64 + cc] = *(const float4*)(vg + (size_t)(j0 + row) * CC + (cc << 2));
            }
        }
        __syncthreads();

        // S-phase: lane computes p(q = qloc, j = jg + 4s) for s = 0..7
        float preg[8];
        #pragma unroll
        for (int s = 0; s < 8; s++) {
            int j = jg + (s << 2);
            const ulonglong2* kp = (const ulonglong2*)&sK[j * 36];
            u64 d0 = 0ull, d1 = 0ull;
            #pragma unroll
            for (int cc = 0; cc < 8; cc++) {
                ulonglong2 kv = kp[cc];      // channels 4cc .. 4cc+3
                d0 = ffma2(qreg[2 * cc],     kv.x, d0);
                d1 = ffma2(qreg[2 * cc + 1], kv.y, d1);
            }
            float2 a = unpack2(d0), bb2 = unpack2(d1);
            float p = __expf(a.x + a.y + bb2.x + bb2.y);
            preg[s] = p;
            lsum += p;
        }

        // PV: acc[q] += p[q][j] * V[j]
        #pragma unroll 4
        for (int j = 0; j < 32; j++) {
            ulonglong2 va = *(const ulonglong2*)&sV[j * 64 + l];
            ulonglong2 vb = *(const ulonglong2*)&sV[j * 64 + l + 32];
            #pragma unroll
            for (int q = 0; q < 8; q++) {
                float pq = __shfl_sync(0xffffffffu, preg[j >> 2], ((j & 3) << 3) | q);
                u64 pp = pack2(pq, pq);
                acc[q][0] = ffma2(pp, va.x, acc[q][0]);
                acc[q][1] = ffma2(pp, va.y, acc[q][1]);
                acc[q][2] = ffma2(pp, vb.x, acc[q][2]);
                acc[q][3] = ffma2(pp, vb.y, acc[q][3]);
            }
        }
    }

    // Row-sum reduction: lanes {q, q+8, q+16, q+24} hold partials for query q
    lsum += __shfl_xor_sync(0xffffffffu, lsum, 8);
    lsum += __shfl_xor_sync(0xffffffffu, lsum, 16);

    const float g = gamma[0];
    #pragma unroll
    for (int q = 0; q < 8; q++) {
        float Lq = __shfl_sync(0xffffffffu, lsum, q);
        float rl = g / Lq;
        int i = i0 + w * 8 + q;
        #pragma unroll
        for (int part = 0; part < 4; part++) {
            int c0 = (part < 2) ? (4 * l + 2 * part) : (128 + 4 * l + 2 * (part - 2));
            float2 v = unpack2(acc[q][part]);
            size_t base = ((size_t)b * CC + c0) * NN + i;
            out[base]      = v.x * rl + res[base];
            out[base + NN] = v.y * rl + res[base + NN];
        }
    }
}

// ---------------------------------------------------------------------------

extern "C" void kernel_launch(void* const* d_in, const int* in_sizes, int n_in,
                              void* d_out, int out_size)
{
    const float* x   = (const float*)d_in[0];
    const float* y   = (const float*)d_in[1];
    const float* wqx = (const float*)d_in[2];
    const float* bqx = (const float*)d_in[3];
    const float* wkx = (const float*)d_in[4];
    const float* bkx = (const float*)d_in[5];
    const float* wvx = (const float*)d_in[6];
    const float* bvx = (const float*)d_in[7];
    const float* wqy = (const float*)d_in[8];
    const float* bqy = (const float*)d_in[9];
    const float* wky = (const float*)d_in[10];
    const float* bky = (const float*)d_in[11];
    const float* wvy = (const float*)d_in[12];
    const float* bvy = (const float*)d_in[13];
    const float* gx  = (const float*)d_in[14];
    const float* gy  = (const float*)d_in[15];
    float* out = (float*)d_out;

    dim3 pgrid(NN / 64, 320 / 32, BB);
    // x-projections -> q1/k1 (branch 1 Q/K), v1 (branch 0 V)
    proj_kernel<<<pgrid, 256>>>(x, wqx, bqx, wkx, bkx, wvx, bvx, 1, 1, 0);
    // y-projections -> q2/k2 (branch 0 Q/K), v2 (branch 1 V)
    proj_kernel<<<pgrid, 256>>>(y, wqy, bqy, wky, bky, wvy, bvy, 0, 0, 1);

    dim3 agrid(NN / 64, BB);
    // out1 = gamma_x * (v1 routed by attn2) + x
    attn_kernel<<<agrid, 256>>>(0, x, gx, out);
    // out2 = gamma_y * (v2 routed by attn1) + y
    attn_kernel<<<agrid, 256>>>(1, y, gy, out + (size_t)BB * CC * NN);
}

// round 4
// speedup vs baseline: 3.2773x; 3.1556x over previous
#include <cuda_runtime.h>
#include <cuda_bf16.h>
#include <math.h>

#define BB 8
#define CC 256
#define NN 2304   // 48*48

typedef unsigned long long u64;
typedef unsigned int u32;

__device__ __forceinline__ u64 pack2(float lo, float hi) {
    u64 r; asm("mov.b64 %0,{%1,%2};" : "=l"(r) : "f"(lo), "f"(hi)); return r;
}
__device__ __forceinline__ float2 unpack2(u64 v) {
    float2 f; asm("mov.b64 {%0,%1},%2;" : "=f"(f.x), "=f"(f.y) : "l"(v)); return f;
}
__device__ __forceinline__ u64 ffma2(u64 a, u64 b, u64 c) {
    u64 d; asm("fma.rn.f32x2 %0,%1,%2,%3;" : "=l"(d) : "l"(a), "l"(b), "l"(c)); return d;
}

__device__ __forceinline__ u32 s2u(const void* p) {
    return (u32)__cvta_generic_to_shared(p);
}
__device__ __forceinline__ void ldsm4(u32* r, u32 a) {
    asm volatile("ldmatrix.sync.aligned.m8n8.x4.shared.b16 {%0,%1,%2,%3},[%4];"
        : "=r"(r[0]), "=r"(r[1]), "=r"(r[2]), "=r"(r[3]) : "r"(a));
}
__device__ __forceinline__ void ldsm2(u32* r, u32 a) {
    asm volatile("ldmatrix.sync.aligned.m8n8.x2.shared.b16 {%0,%1},[%2];"
        : "=r"(r[0]), "=r"(r[1]) : "r"(a));
}
__device__ __forceinline__ void ldsm2t(u32* r, u32 a) {
    asm volatile("ldmatrix.sync.aligned.m8n8.x2.trans.shared.b16 {%0,%1},[%2];"
        : "=r"(r[0]), "=r"(r[1]) : "r"(a));
}
__device__ __forceinline__ void mma_bf16(float* c, const u32* a, const u32* b) {
    asm volatile("mma.sync.aligned.m16n8k16.row.col.f32.bf16.bf16.f32 "
        "{%0,%1,%2,%3},{%4,%5,%6,%7},{%8,%9},{%0,%1,%2,%3};"
        : "+f"(c[0]), "+f"(c[1]), "+f"(c[2]), "+f"(c[3])
        : "r"(a[0]), "r"(a[1]), "r"(a[2]), "r"(a[3]), "r"(b[0]), "r"(b[1]));
}
// packs {lo -> bits[15:0], hi -> bits[31:16]}
__device__ __forceinline__ u32 cvt_bf16x2(float hi, float lo) {
    u32 r; asm("cvt.rn.bf16x2.f32 %0,%1,%2;" : "=r"(r) : "f"(hi), "f"(lo)); return r;
}

// Scratch (cudaMalloc banned -> __device__ globals). bf16 projections.
// branch 0: Q/K from y-projections (attn2), V = v1 (from x)  -> out1
// branch 1: Q/K from x-projections (attn1), V = v2 (from y)  -> out2
__device__ __nv_bfloat16 g_qh[2][BB][NN][32];
__device__ __nv_bfloat16 g_ql[2][BB][NN][32];
__device__ __nv_bfloat16 g_kh[2][BB][NN][32];
__device__ __nv_bfloat16 g_kl[2][BB][NN][32];
__device__ __nv_bfloat16 g_vb[2][BB][NN][CC];

// ---------------------------------------------------------------------------
// Projection GEMM: out[b][n][o] = sum_c W[o][c] * in[b][c][n] + bias[o]
// O space = [q(32) | k(32) | v(256)] = 320 outputs, selected by blockIdx.y.
// Epilogue emits bf16 (hi/lo split for q,k; single bf16 for v).
// ---------------------------------------------------------------------------
__global__ __launch_bounds__(256) void proj_kernel(
    const float* __restrict__ in,
    const float* __restrict__ wq, const float* __restrict__ bq,
    const float* __restrict__ wk, const float* __restrict__ bk,
    const float* __restrict__ wv, const float* __restrict__ bv,
    int qb, int kb, int vb)
{
    const int b  = blockIdx.z;
    const int n0 = blockIdx.x * 64;
    const int o0 = blockIdx.y * 32;

    __shared__ float sW[32][33];
    __shared__ float sX[32][68];

    const int tid = threadIdx.x;
    const int ox  = tid & 15;
    const int ny  = tid >> 4;

    u64 acc2[2][2] = {{0ull, 0ull}, {0ull, 0ull}};
    const float* inb = in + (size_t)b * CC * NN;

    for (int k0 = 0; k0 < CC; k0 += 32) {
        {
            int row = tid >> 3;
            int c4  = (tid & 7) << 2;
            int o   = o0 + row;
            const float* wrow = (o < 32) ? (wq + (size_t)o * CC)
                              : (o < 64) ? (wk + (size_t)(o - 32) * CC)
                                         : (wv + (size_t)(o - 64) * CC);
            float4 w4 = *(const float4*)(wrow + k0 + c4);
            sW[row][c4+0] = w4.x; sW[row][c4+1] = w4.y;
            sW[row][c4+2] = w4.z; sW[row][c4+3] = w4.w;
        }
        {
            int r  = tid >> 4;
            int c4 = (tid & 15) << 2;
            float4 a0 = *(const float4*)(inb + (size_t)(k0 + r)      * NN + n0 + c4);
            float4 a1 = *(const float4*)(inb + (size_t)(k0 + r + 16) * NN + n0 + c4);
            *(float4*)&sX[r][c4]      = a0;
            *(float4*)&sX[r + 16][c4] = a1;
        }
        __syncthreads();

        #pragma unroll
        for (int cc = 0; cc < 32; cc++) {
            float w0 = sW[ox][cc];
            float w1 = sW[ox + 16][cc];
            ulonglong2 xv = *(const ulonglong2*)&sX[cc][ny << 2];
            u64 p0 = pack2(w0, w0);
            u64 p1 = pack2(w1, w1);
            acc2[0][0] = ffma2(p0, xv.x, acc2[0][0]);
            acc2[0][1] = ffma2(p0, xv.y, acc2[0][1]);
            acc2[1][0] = ffma2(p1, xv.x, acc2[1][0]);
            acc2[1][1] = ffma2(p1, xv.y, acc2[1][1]);
        }
        __syncthreads();
    }

    #pragma unroll
    for (int half = 0; half < 2; half++) {
        int o = o0 + ox + half * 16;
        float2 v01 = unpack2(acc2[half][0]);
        float2 v23 = unpack2(acc2[half][1]);
        float vals[4] = {v01.x, v01.y, v23.x, v23.y};
        #pragma unroll
        for (int i = 0; i < 4; i++) {
            int n = n0 + (ny << 2) + i;
            if (o < 32) {
                float v = vals[i] + bq[o];
                __nv_bfloat16 h = __float2bfloat16(v);
                g_qh[qb][b][n][o] = h;
                g_ql[qb][b][n][o] = __float2bfloat16(v - __bfloat162float(h));
            } else if (o < 64) {
                float v = vals[i] + bk[o - 32];
                __nv_bfloat16 h = __float2bfloat16(v);
                g_kh[kb][b][n][o - 32] = h;
                g_kl[kb][b][n][o - 32] = __float2bfloat16(v - __bfloat162float(h));
            } else {
                float v = vals[i] + bv[o - 64];
                g_vb[vb][b][n][o - 64] = __float2bfloat16(v);
            }
        }
    }
}

// ---------------------------------------------------------------------------
// Tensor-core fused attention + residual.
// Block: 64 queries, 8 warps. Warp w: rg = w&3 (query rows rg*16..+15),
// ch = w>>2 (S-phase j half / PV channel half).
// Per 32-j tile: S = Q.K^T via split-bf16 mma, exp -> bf16 P in smem,
// PV via bf16 mma. No-max softmax (logits bounded ~35).
// ---------------------------------------------------------------------------
__global__ __launch_bounds__(256, 2) void attn_kernel(
    int br, const float* __restrict__ res, const float* __restrict__ gamma,
    float* __restrict__ out)
{
    const int b   = blockIdx.y;
    const int i0  = blockIdx.x * 64;
    const int tid = threadIdx.x;
    const int w   = tid >> 5;
    const int l   = tid & 31;
    const int rg  = w & 3;
    const int ch  = w >> 2;
    const int grp = l >> 2;
    const int t4  = l & 3;
    const int q0  = rg * 16;

    __shared__ __align__(16) __nv_bfloat16 sKh[32][40];
    __shared__ __align__(16) __nv_bfloat16 sKl[32][40];
    __shared__ __align__(16) __nv_bfloat16 sV [32][264];
    __shared__ __align__(16) __nv_bfloat16 sP [64][40];
    __shared__ __align__(16) __nv_bfloat16 sQh[64][40];
    __shared__ __align__(16) __nv_bfloat16 sQl[64][40];
    __shared__ float sLred[2][64];

    // Stage Q hi/lo: 64 rows x 32 cols bf16 each (256 float4 per array)
    {
        int row = tid >> 2, c8 = (tid & 3) * 8;
        *(float4*)&sQh[row][c8] = *(const float4*)&g_qh[br][b][i0 + row][c8];
        *(float4*)&sQl[row][c8] = *(const float4*)&g_ql[br][b][i0 + row][c8];
    }
    __syncthreads();

    // Persistent Q fragments (A of m16n8k16): rows q0..q0+15, k chunks 0/1
    u32 qh[2][4], ql[2][4];
    {
        int row = q0 + (l & 15);
        int cofs = (l & 16) ? 8 : 0;
        #pragma unroll
        for (int kc = 0; kc < 2; kc++) {
            ldsm4(qh[kc], s2u(&sQh[row][kc * 16 + cofs]));
            ldsm4(ql[kc], s2u(&sQl[row][kc * 16 + cofs]));
        }
    }

    float acc[16][4];
    #pragma unroll
    for (int t = 0; t < 16; t++)
        #pragma unroll
        for (int i = 0; i < 4; i++) acc[t][i] = 0.f;
    float lsum0 = 0.f, lsum1 = 0.f;

    const __nv_bfloat16* khg = &g_kh[br][b][0][0];
    const __nv_bfloat16* klg = &g_kl[br][b][0][0];
    const __nv_bfloat16* vg  = &g_vb[br][b][0][0];

    for (int jt = 0; jt < NN / 32; jt++) {
        const int j0 = jt * 32;
        __syncthreads();
        // Load K hi/lo (32x32 bf16 each) and V (32x256 bf16)
        {
            int i7 = tid & 127;
            int row = i7 >> 2, c8 = (i7 & 3) * 8;
            if (tid < 128)
                *(float4*)&sKh[row][c8] = *(const float4*)(khg + (size_t)(j0 + row) * 32 + c8);
            else
                *(float4*)&sKl[row][c8] = *(const float4*)(klg + (size_t)(j0 + row) * 32 + c8);
            #pragma unroll
            for (int it = 0; it < 4; it++) {
                int idx = tid + it * 256;
                int vr = idx >> 5, vc8 = (idx & 31) * 8;
                *(float4*)&sV[vr][vc8] = *(const float4*)(vg + (size_t)(j0 + vr) * CC + vc8);
            }
        }
        __syncthreads();

        // S phase: warp computes S[q0..q0+15][ch*16 .. ch*16+15] (2 n8 tiles)
        #pragma unroll
        for (int tile = 0; tile < 2; tile++) {
            int jn = ch * 16 + tile * 8;
            float c[4] = {0.f, 0.f, 0.f, 0.f};
            int lrow = l & 15;
            int brow = jn + (lrow & 7);
            int bofs = (lrow & 8) ? 8 : 0;
            #pragma unroll
            for (int kc = 0; kc < 2; kc++) {
                u32 bh[2], bl[2];
                ldsm2(bh, s2u(&sKh[brow][kc * 16 + bofs]));
                ldsm2(bl, s2u(&sKl[brow][kc * 16 + bofs]));
                mma_bf16(c, qh[kc], bh);
                mma_bf16(c, qh[kc], bl);
                mma_bf16(c, ql[kc], bh);
            }
            float e0 = __expf(c[0]);
            float e1 = __expf(c[1]);
            float e2 = __expf(c[2]);
            float e3 = __expf(c[3]);
            lsum0 += e0 + e1;
            lsum1 += e2 + e3;
            *(u32*)&sP[q0 + grp][jn + 2 * t4]     = cvt_bf16x2(e1, e0);
            *(u32*)&sP[q0 + 8 + grp][jn + 2 * t4] = cvt_bf16x2(e3, e2);
        }
        __syncthreads();

        // PV phase: A = P[q0..q0+15][0..31], B = V tiles (ch half: cols ch*128..+127)
        u32 pa[2][4];
        {
            int row = q0 + (l & 15);
            int cofs = (l & 16) ? 8 : 0;
            #pragma unroll
            for (int kj = 0; kj < 2; kj++)
                ldsm4(pa[kj], s2u(&sP[row][kj * 16 + cofs]));
        }
        #pragma unroll
        for (int t = 0; t < 16; t++) {
            int n0 = ch * 128 + t * 8;
            #pragma unroll
            for (int kj = 0; kj < 2; kj++) {
                u32 bv[2];
                ldsm2t(bv, s2u(&sV[kj * 16 + (l & 15)][n0]));
                mma_bf16(acc[t], pa[kj], bv);
            }
        }
    }

    // lsum: quad reduce (lanes sharing grp hold disjoint cols), then combine halves
    lsum0 += __shfl_xor_sync(0xffffffffu, lsum0, 1);
    lsum0 += __shfl_xor_sync(0xffffffffu, lsum0, 2);
    lsum1 += __shfl_xor_sync(0xffffffffu, lsum1, 1);
    lsum1 += __shfl_xor_sync(0xffffffffu, lsum1, 2);
    if (t4 == 0) {
        sLred[ch][q0 + grp]     = lsum0;
        sLred[ch][q0 + 8 + grp] = lsum1;
    }
    __syncthreads();

    const float g = gamma[0];
    float L0 = sLred[0][q0 + grp]     + sLred[1][q0 + grp];
    float L1 = sLred[0][q0 + 8 + grp] + sLred[1][q0 + 8 + grp];
    float rl0 = g / L0, rl1 = g / L1;
    int ir0 = i0 + q0 + grp;
    int ir1 = ir0 + 8;
    #pragma unroll
    for (int t = 0; t < 16; t++) {
        int c0 = ch * 128 + t * 8 + 2 * t4;
        size_t base = ((size_t)b * CC + c0) * NN;
        out[base + ir0]      = acc[t][0] * rl0 + res[base + ir0];
        out[base + NN + ir0] = acc[t][1] * rl0 + res[base + NN + ir0];
        out[base + ir1]      = acc[t][2] * rl1 + res[base + ir1];
        out[base + NN + ir1] = acc[t][3] * rl1 + res[base + NN + ir1];
    }
}

// ---------------------------------------------------------------------------

extern "C" void kernel_launch(void* const* d_in, const int* in_sizes, int n_in,
                              void* d_out, int out_size)
{
    const float* x   = (const float*)d_in[0];
    const float* y   = (const float*)d_in[1];
    const float* wqx = (const float*)d_in[2];
    const float* bqx = (const float*)d_in[3];
    const float* wkx = (const float*)d_in[4];
    const float* bkx = (const float*)d_in[5];
    const float* wvx = (const float*)d_in[6];
    const float* bvx = (const float*)d_in[7];
    const float* wqy = (const float*)d_in[8];
    const float* bqy = (const float*)d_in[9];
    const float* wky = (const float*)d_in[10];
    const float* bky = (const float*)d_in[11];
    const float* wvy = (const float*)d_in[12];
    const float* bvy = (const float*)d_in[13];
    const float* gx  = (const float*)d_in[14];
    const float* gy  = (const float*)d_in[15];
    float* out = (float*)d_out;

    dim3 pgrid(NN / 64, 320 / 32, BB);
    // x-projections -> q1/k1 (branch 1 Q/K), v1 (branch 0 V)
    proj_kernel<<<pgrid, 256>>>(x, wqx, bqx, wkx, bkx, wvx, bvx, 1, 1, 0);
    // y-projections -> q2/k2 (branch 0 Q/K), v2 (branch 1 V)
    proj_kernel<<<pgrid, 256>>>(y, wqy, bqy, wky, bky, wvy, bvy, 0, 0, 1);

    dim3 agrid(NN / 64, BB);
    // out1 = gamma_x * (v1 routed by attn2) + x
    attn_kernel<<<agrid, 256>>>(0, x, gx, out);
    // out2 = gamma_y * (v2 routed by attn1) + y
    attn_kernel<<<agrid, 256>>>(1, y, gy, out + (size_t)BB * CC * NN);
}

// round 5
// speedup vs baseline: 3.6383x; 1.1101x over previous
#include <cuda_runtime.h>
#include <cuda_bf16.h>
#include <math.h>

#define BB 8
#define CC 256
#define NN 2304   // 48*48
#define NT (NN/32)

typedef unsigned long long u64;
typedef unsigned int u32;

__device__ __forceinline__ u64 pack2(float lo, float hi) {
    u64 r; asm("mov.b64 %0,{%1,%2};" : "=l"(r) : "f"(lo), "f"(hi)); return r;
}
__device__ __forceinline__ float2 unpack2(u64 v) {
    float2 f; asm("mov.b64 {%0,%1},%2;" : "=f"(f.x), "=f"(f.y) : "l"(v)); return f;
}
__device__ __forceinline__ u64 ffma2(u64 a, u64 b, u64 c) {
    u64 d; asm("fma.rn.f32x2 %0,%1,%2,%3;" : "=l"(d) : "l"(a), "l"(b), "l"(c)); return d;
}
__device__ __forceinline__ u32 s2u(const void* p) {
    return (u32)__cvta_generic_to_shared(p);
}
__device__ __forceinline__ void ldsm4(u32* r, u32 a) {
    asm volatile("ldmatrix.sync.aligned.m8n8.x4.shared.b16 {%0,%1,%2,%3},[%4];"
        : "=r"(r[0]), "=r"(r[1]), "=r"(r[2]), "=r"(r[3]) : "r"(a));
}
__device__ __forceinline__ void ldsm4t(u32* r, u32 a) {
    asm volatile("ldmatrix.sync.aligned.m8n8.x4.trans.shared.b16 {%0,%1,%2,%3},[%4];"
        : "=r"(r[0]), "=r"(r[1]), "=r"(r[2]), "=r"(r[3]) : "r"(a));
}
__device__ __forceinline__ void mma_bf16(float* c, const u32* a, u32 b0, u32 b1) {
    asm volatile("mma.sync.aligned.m16n8k16.row.col.f32.bf16.bf16.f32 "
        "{%0,%1,%2,%3},{%4,%5,%6,%7},{%8,%9},{%0,%1,%2,%3};"
        : "+f"(c[0]), "+f"(c[1]), "+f"(c[2]), "+f"(c[3])
        : "r"(a[0]), "r"(a[1]), "r"(a[2]), "r"(a[3]), "r"(b0), "r"(b1));
}
// packs {lo -> bits[15:0], hi -> bits[31:16]}
__device__ __forceinline__ u32 cvt_bf16x2(float hi, float lo) {
    u32 r; asm("cvt.rn.bf16x2.f32 %0,%1,%2;" : "=r"(r) : "f"(hi), "f"(lo)); return r;
}
__device__ __forceinline__ void cpasync16(u32 dst, const void* src) {
    asm volatile("cp.async.cg.shared.global [%0],[%1],16;" :: "r"(dst), "l"(src));
}
__device__ __forceinline__ void cpcommit() { asm volatile("cp.async.commit_group;"); }
__device__ __forceinline__ void cpwait1()  { asm volatile("cp.async.wait_group 1;"); }
__device__ __forceinline__ void cpwait0()  { asm volatile("cp.async.wait_group 0;"); }

// Scratch (cudaMalloc banned -> __device__ globals). bf16 projections.
// branch 0: Q/K from y-projections (attn2), V = v1 (from x)  -> out1
// branch 1: Q/K from x-projections (attn1), V = v2 (from y)  -> out2
__device__ __nv_bfloat16 g_qh[2][BB][NN][32];
__device__ __nv_bfloat16 g_ql[2][BB][NN][32];
__device__ __nv_bfloat16 g_kh[2][BB][NN][32];
__device__ __nv_bfloat16 g_kl[2][BB][NN][32];
__device__ __nv_bfloat16 g_vb[2][BB][NN][CC];

// ---------------------------------------------------------------------------
// Projection GEMM: out[b][n][o] = sum_c W[o][c] * in[b][c][n] + bias[o]
// ---------------------------------------------------------------------------
__global__ __launch_bounds__(256) void proj_kernel(
    const float* __restrict__ in,
    const float* __restrict__ wq, const float* __restrict__ bq,
    const float* __restrict__ wk, const float* __restrict__ bk,
    const float* __restrict__ wv, const float* __restrict__ bv,
    int qb, int kb, int vb)
{
    const int b  = blockIdx.z;
    const int n0 = blockIdx.x * 64;
    const int o0 = blockIdx.y * 32;

    __shared__ float sW[32][33];
    __shared__ float sX[32][68];

    const int tid = threadIdx.x;
    const int ox  = tid & 15;
    const int ny  = tid >> 4;

    u64 acc2[2][2] = {{0ull, 0ull}, {0ull, 0ull}};
    const float* inb = in + (size_t)b * CC * NN;

    for (int k0 = 0; k0 < CC; k0 += 32) {
        {
            int row = tid >> 3;
            int c4  = (tid & 7) << 2;
            int o   = o0 + row;
            const float* wrow = (o < 32) ? (wq + (size_t)o * CC)
                              : (o < 64) ? (wk + (size_t)(o - 32) * CC)
                                         : (wv + (size_t)(o - 64) * CC);
            float4 w4 = *(const float4*)(wrow + k0 + c4);
            sW[row][c4+0] = w4.x; sW[row][c4+1] = w4.y;
            sW[row][c4+2] = w4.z; sW[row][c4+3] = w4.w;
        }
        {
            int r  = tid >> 4;
            int c4 = (tid & 15) << 2;
            float4 a0 = *(const float4*)(inb + (size_t)(k0 + r)      * NN + n0 + c4);
            float4 a1 = *(const float4*)(inb + (size_t)(k0 + r + 16) * NN + n0 + c4);
            *(float4*)&sX[r][c4]      = a0;
            *(float4*)&sX[r + 16][c4] = a1;
        }
        __syncthreads();

        #pragma unroll
        for (int cc = 0; cc < 32; cc++) {
            float w0 = sW[ox][cc];
            float w1 = sW[ox + 16][cc];
            ulonglong2 xv = *(const ulonglong2*)&sX[cc][ny << 2];
            u64 p0 = pack2(w0, w0);
            u64 p1 = pack2(w1, w1);
            acc2[0][0] = ffma2(p0, xv.x, acc2[0][0]);
            acc2[0][1] = ffma2(p0, xv.y, acc2[0][1]);
            acc2[1][0] = ffma2(p1, xv.x, acc2[1][0]);
            acc2[1][1] = ffma2(p1, xv.y, acc2[1][1]);
        }
        __syncthreads();
    }

    #pragma unroll
    for (int half = 0; half < 2; half++) {
        int o = o0 + ox + half * 16;
        float2 v01 = unpack2(acc2[half][0]);
        float2 v23 = unpack2(acc2[half][1]);
        float vals[4] = {v01.x, v01.y, v23.x, v23.y};
        #pragma unroll
        for (int i = 0; i < 4; i++) {
            int n = n0 + (ny << 2) + i;
            if (o < 32) {
                float v = vals[i] + bq[o];
                __nv_bfloat16 h = __float2bfloat16(v);
                g_qh[qb][b][n][o] = h;
                g_ql[qb][b][n][o] = __float2bfloat16(v - __bfloat162float(h));
            } else if (o < 64) {
                float v = vals[i] + bk[o - 32];
                __nv_bfloat16 h = __float2bfloat16(v);
                g_kh[kb][b][n][o - 32] = h;
                g_kl[kb][b][n][o - 32] = __float2bfloat16(v - __bfloat162float(h));
            } else {
                float v = vals[i] + bv[o - 64];
                g_vb[vb][b][n][o - 64] = __float2bfloat16(v);
            }
        }
    }
}

// ---------------------------------------------------------------------------
// Tensor-core fused attention, register-resident P, cp.async double-buffered.
// Block: 64 queries, 8 warps. Warp w: rg = w&3 (16 query rows), ch = w>>2
// (PV channel half). Each warp computes the FULL 32-j S tile for its rows
// (duplicated across ch), exp's in-register, packs A-frags, then PV.
// No-max softmax (logits bounded ~35, safe in fp32).
// ---------------------------------------------------------------------------
__global__ __launch_bounds__(256, 2) void attn_kernel(
    const float* __restrict__ x, const float* __restrict__ y,
    const float* __restrict__ gx, const float* __restrict__ gy,
    float* __restrict__ out)
{
    const int br  = blockIdx.z;
    const int b   = blockIdx.y;
    const int i0  = blockIdx.x * 64;
    const int tid = threadIdx.x;
    const int w   = tid >> 5;
    const int l   = tid & 31;
    const int rg  = w & 3;
    const int ch  = w >> 2;
    const int grp = l >> 2;
    const int t4  = l & 3;
    const int q0  = rg * 16;

    const float* res = br ? y : x;
    const float* gmm = br ? gy : gx;
    float* outp = out + (size_t)br * BB * CC * NN;

    // dynamic smem layout (bf16 elements)
    // sKh[2][32][40], sKl[2][32][40], sV[2][32][264], sQh[64][40], sQl[64][40]
    extern __shared__ __align__(16) __nv_bfloat16 smem[];
    __nv_bfloat16* sKh = smem;                    // 2*1280
    __nv_bfloat16* sKl = sKh + 2 * 32 * 40;       // 2*1280
    __nv_bfloat16* sV  = sKl + 2 * 32 * 40;       // 2*8448
    __nv_bfloat16* sQh = sV  + 2 * 32 * 264;      // 2560
    __nv_bfloat16* sQl = sQh + 64 * 40;           // 2560

    // Stage Q hi/lo: 64 rows x 32 cols bf16 each
    {
        int row = tid >> 2, c8 = (tid & 3) * 8;
        *(float4*)&sQh[row * 40 + c8] = *(const float4*)&g_qh[br][b][i0 + row][c8];
        *(float4*)&sQl[row * 40 + c8] = *(const float4*)&g_ql[br][b][i0 + row][c8];
    }
    __syncthreads();

    // Persistent Q fragments (A of m16n8k16): rows q0..q0+15, k chunks 0/1
    u32 qh[2][4], ql[2][4];
    {
        int row = q0 + (l & 15);
        int cofs = (l & 16) ? 8 : 0;
        #pragma unroll
        for (int kc = 0; kc < 2; kc++) {
            ldsm4(qh[kc], s2u(&sQh[row * 40 + kc * 16 + cofs]));
            ldsm4(ql[kc], s2u(&sQl[row * 40 + kc * 16 + cofs]));
        }
    }

    const __nv_bfloat16* khg = &g_kh[br][b][0][0];
    const __nv_bfloat16* klg = &g_kl[br][b][0][0];
    const __nv_bfloat16* vg  = &g_vb[br][b][0][0];

    // cp.async staging: thread -> 2 K chunks? (256 K chunks total) + 4 V chunks
    // K: tid<128 -> Kh chunk, else Kl: row = (tid&127)>>2, c8 = ((tid&127)&3)*8
    const int krow = (tid & 127) >> 2;
    const int kc8  = ((tid & 127) & 3) * 8;
    const bool khi = tid < 128;

    float acc[16][4];
    #pragma unroll
    for (int t = 0; t < 16; t++)
        #pragma unroll
        for (int i = 0; i < 4; i++) acc[t][i] = 0.f;
    float lsA = 0.f, lsB = 0.f;

    // prologue: load tile 0 into buf 0
    {
        __nv_bfloat16* dK = khi ? sKh : sKl;
        const __nv_bfloat16* gK = khi ? khg : klg;
        cpasync16(s2u(&dK[krow * 40 + kc8]), gK + (size_t)krow * 32 + kc8);
        #pragma unroll
        for (int it = 0; it < 4; it++) {
            int idx = tid + it * 256;
            int vr = idx >> 5, vc8 = (idx & 31) * 8;
            cpasync16(s2u(&sV[vr * 264 + vc8]), vg + (size_t)vr * CC + vc8);
        }
        cpcommit();
    }

    const int ldA = (l & 16) ? 8 : 0;         // ldsm second-half col offset
    const int krA = ((l >> 4) << 3) + (l & 7);  // K ldsm4 row within 16-grp
    const int kcA = ((l >> 3) & 1) * 8;         // K ldsm4 col offset

    for (int jt = 0; jt < NT; jt++) {
        const int buf = jt & 1;
        if (jt + 1 < NT) {
            // issue loads for tile jt+1 into buffer buf^1
            const int nb = buf ^ 1;
            const size_t j1 = (size_t)(jt + 1) * 32;
            __nv_bfloat16* dK = (khi ? sKh : sKl) + nb * 32 * 40;
            const __nv_bfloat16* gK = khi ? khg : klg;
            cpasync16(s2u(&dK[krow * 40 + kc8]), gK + (j1 + krow) * 32 + kc8);
            __nv_bfloat16* dV = sV + nb * 32 * 264;
            #pragma unroll
            for (int it = 0; it < 4; it++) {
                int idx = tid + it * 256;
                int vr = idx >> 5, vc8 = (idx & 31) * 8;
                cpasync16(s2u(&dV[vr * 264 + vc8]), vg + (j1 + vr) * CC + vc8);
            }
            cpcommit();
            cpwait1();
        } else {
            cpwait0();
        }
        __syncthreads();

        const __nv_bfloat16* bKh = sKh + buf * 32 * 40;
        const __nv_bfloat16* bKl = sKl + buf * 32 * 40;
        const __nv_bfloat16* bV  = sV  + buf * 32 * 264;

        // S phase: 4 n8 j-tiles (full 32 j) for this warp's 16 rows
        float sc[4][4];
        #pragma unroll
        for (int t = 0; t < 4; t++)
            #pragma unroll
            for (int i = 0; i < 4; i++) sc[t][i] = 0.f;

        #pragma unroll
        for (int jg = 0; jg < 2; jg++) {
            #pragma unroll
            for (int kc = 0; kc < 2; kc++) {
                u32 kh4[4], kl4[4];
                ldsm4(kh4, s2u(&bKh[(jg * 16 + krA) * 40 + kc * 16 + kcA]));
                ldsm4(kl4, s2u(&bKl[(jg * 16 + krA) * 40 + kc * 16 + kcA]));
                mma_bf16(sc[jg * 2],     qh[kc], kh4[0], kh4[1]);
                mma_bf16(sc[jg * 2],     qh[kc], kl4[0], kl4[1]);
                mma_bf16(sc[jg * 2],     ql[kc], kh4[0], kh4[1]);
                mma_bf16(sc[jg * 2 + 1], qh[kc], kh4[2], kh4[3]);
                mma_bf16(sc[jg * 2 + 1], qh[kc], kl4[2], kl4[3]);
                mma_bf16(sc[jg * 2 + 1], ql[kc], kh4[2], kh4[3]);
            }
        }

        // exp + pack P A-frags in registers
        u32 pa[2][4];
        #pragma unroll
        for (int t = 0; t < 4; t++) {
            float e0 = __expf(sc[t][0]);
            float e1 = __expf(sc[t][1]);
            float e2 = __expf(sc[t][2]);
            float e3 = __expf(sc[t][3]);
            lsA += e0 + e1;
            lsB += e2 + e3;
            int kj = t >> 1, sub = (t & 1) * 2;
            pa[kj][sub]     = cvt_bf16x2(e1, e0);
            pa[kj][sub + 1] = cvt_bf16x2(e3, e2);
        }

        // PV: B = V frags via ldsm4t
        #pragma unroll
        for (int g = 0; g < 8; g++) {
            int n0 = ch * 128 + g * 16 + ldA;
            #pragma unroll
            for (int kj = 0; kj < 2; kj++) {
                u32 vb4[4];
                ldsm4t(vb4, s2u(&bV[(kj * 16 + (l & 15)) * 264 + n0]));
                mma_bf16(acc[g * 2],     pa[kj], vb4[0], vb4[1]);
                mma_bf16(acc[g * 2 + 1], pa[kj], vb4[2], vb4[3]);
            }
        }
        __syncthreads();   // all reads of buf done before it is overwritten
    }

    // lsum: quad reduce (lanes in a quad hold disjoint j columns)
    lsA += __shfl_xor_sync(0xffffffffu, lsA, 1);
    lsA += __shfl_xor_sync(0xffffffffu, lsA, 2);
    lsB += __shfl_xor_sync(0xffffffffu, lsB, 1);
    lsB += __shfl_xor_sync(0xffffffffu, lsB, 2);

    const float g = gmm[0];
    float rl0 = g / lsA, rl1 = g / lsB;
    int ir0 = i0 + q0 + grp;
    int ir1 = ir0 + 8;
    #pragma unroll
    for (int t = 0; t < 16; t++) {
        int c0 = ch * 128 + t * 8 + 2 * t4;
        size_t base = ((size_t)b * CC + c0) * NN;
        outp[base + ir0]      = acc[t][0] * rl0 + res[base + ir0];
        outp[base + NN + ir0] = acc[t][1] * rl0 + res[base + NN + ir0];
        outp[base + ir1]      = acc[t][2] * rl1 + res[base + ir1];
        outp[base + NN + ir1] = acc[t][3] * rl1 + res[base + NN + ir1];
    }
}

// ---------------------------------------------------------------------------

extern "C" void kernel_launch(void* const* d_in, const int* in_sizes, int n_in,
                              void* d_out, int out_size)
{
    const float* x   = (const float*)d_in[0];
    const float* y   = (const float*)d_in[1];
    const float* wqx = (const float*)d_in[2];
    const float* bqx = (const float*)d_in[3];
    const float* wkx = (const float*)d_in[4];
    const float* bkx = (const float*)d_in[5];
    const float* wvx = (const float*)d_in[6];
    const float* bvx = (const float*)d_in[7];
    const float* wqy = (const float*)d_in[8];
    const float* bqy = (const float*)d_in[9];
    const float* wky = (const float*)d_in[10];
    const float* bky = (const float*)d_in[11];
    const float* wvy = (const float*)d_in[12];
    const float* bvy = (const float*)d_in[13];
    const float* gx  = (const float*)d_in[14];
    const float* gy  = (const float*)d_in[15];
    float* out = (float*)d_out;

    // smem: (2*1280 + 2*1280 + 2*8448 + 2560 + 2560)*2 bytes
    const int ATTN_SMEM = (2*1280 + 2*1280 + 2*8448 + 2560 + 2560) * 2;
    static int cfgd = 0;
    if (!cfgd) {
        cudaFuncSetAttribute(attn_kernel, cudaFuncAttributeMaxDynamicSharedMemorySize, ATTN_SMEM);
        cfgd = 1;
    }

    dim3 pgrid(NN / 64, 320 / 32, BB);
    // x-projections -> q1/k1 (branch 1 Q/K), v1 (branch 0 V)
    proj_kernel<<<pgrid, 256>>>(x, wqx, bqx, wkx, bkx, wvx, bvx, 1, 1, 0);
    // y-projections -> q2/k2 (branch 0 Q/K), v2 (branch 1 V)
    proj_kernel<<<pgrid, 256>>>(y, wqy, bqy, wky, bky, wvy, bvy, 0, 0, 1);

    dim3 agrid(NN / 64, BB, 2);
    attn_kernel<<<agrid, 256, ATTN_SMEM>>>(x, y, gx, gy, out);
}

// round 8
// speedup vs baseline: 5.0149x; 1.3784x over previous
#include <cuda_runtime.h>
#include <cuda_bf16.h>
#include <math.h>

#define BB 8
#define CC 256
#define NN 2304   // 48*48
#define NT (NN/32)

typedef unsigned long long u64;
typedef unsigned int u32;

__device__ __forceinline__ u32 s2u(const void* p) {
    return (u32)__cvta_generic_to_shared(p);
}
__device__ __forceinline__ void ldsm4(u32* r, u32 a) {
    asm volatile("ldmatrix.sync.aligned.m8n8.x4.shared.b16 {%0,%1,%2,%3},[%4];"
        : "=r"(r[0]), "=r"(r[1]), "=r"(r[2]), "=r"(r[3]) : "r"(a));
}
__device__ __forceinline__ void ldsm4t(u32* r, u32 a) {
    asm volatile("ldmatrix.sync.aligned.m8n8.x4.trans.shared.b16 {%0,%1,%2,%3},[%4];"
        : "=r"(r[0]), "=r"(r[1]), "=r"(r[2]), "=r"(r[3]) : "r"(a));
}
__device__ __forceinline__ void mma_bf16(float* c, const u32* a, u32 b0, u32 b1) {
    asm volatile("mma.sync.aligned.m16n8k16.row.col.f32.bf16.bf16.f32 "
        "{%0,%1,%2,%3},{%4,%5,%6,%7},{%8,%9},{%0,%1,%2,%3};"
        : "+f"(c[0]), "+f"(c[1]), "+f"(c[2]), "+f"(c[3])
        : "r"(a[0]), "r"(a[1]), "r"(a[2]), "r"(a[3]), "r"(b0), "r"(b1));
}
// packs {lo -> bits[15:0], hi -> bits[31:16]}
__device__ __forceinline__ u32 cvt_bf16x2(float hi, float lo) {
    u32 r; asm("cvt.rn.bf16x2.f32 %0,%1,%2;" : "=r"(r) : "f"(hi), "f"(lo)); return r;
}
__device__ __forceinline__ void cpasync16(u32 dst, const void* src) {
    asm volatile("cp.async.cg.shared.global [%0],[%1],16;" :: "r"(dst), "l"(src));
}
__device__ __forceinline__ void cpcommit() { asm volatile("cp.async.commit_group;"); }
__device__ __forceinline__ void cpwait1()  { asm volatile("cp.async.wait_group 1;"); }
__device__ __forceinline__ void cpwait0()  { asm volatile("cp.async.wait_group 0;"); }

// Scratch (cudaMalloc banned -> __device__ globals). bf16 projections.
// branch 0: Q/K from y-projections (attn2), V = v1 (from x)  -> out1
// branch 1: Q/K from x-projections (attn1), V = v2 (from y)  -> out2
__device__ __nv_bfloat16 g_qh[2][BB][NN][32];
__device__ __nv_bfloat16 g_ql[2][BB][NN][32];
__device__ __nv_bfloat16 g_kh[2][BB][NN][32];
__device__ __nv_bfloat16 g_kl[2][BB][NN][32];
__device__ __nv_bfloat16 g_vb[2][BB][NN][CC];

// split fp32 -> bf16 hi/lo, pack 8 values into 16B stores
__device__ __forceinline__ void split_store8(const float* v,
                                             __nv_bfloat16* hd, __nv_bfloat16* ld) {
    u32 hw[4], lw[4];
    #pragma unroll
    for (int i = 0; i < 4; i++) {
        float a = v[2*i], b = v[2*i+1];
        __nv_bfloat16 ha = __float2bfloat16(a), hb = __float2bfloat16(b);
        hw[i] = cvt_bf16x2(__bfloat162float(hb), __bfloat162float(ha));
        lw[i] = cvt_bf16x2(b - __bfloat162float(hb), a - __bfloat162float(ha));
    }
    *(uint4*)hd = make_uint4(hw[0], hw[1], hw[2], hw[3]);
    *(uint4*)ld = make_uint4(lw[0], lw[1], lw[2], lw[3]);
}

// ---------------------------------------------------------------------------
// Tensor-core projection GEMM: out[o][n] = sum_c W[o][c] * X[c][n] + bias[o]
// Split-bf16 (3 mma passes) for fp32-level accuracy on q/k logits path.
// Block tile: 64 o x 64 n; k-chunks of 32. 8 warps: rg=w&3 (o rows), ng=w>>2
// (n half). Epilogue: smem transpose -> coalesced bf16 stores in [n][o] layout.
// grid: (NN/64, 320/64, 2*BB);  z: inp = z>>3, b = z&7.
// ---------------------------------------------------------------------------
__global__ __launch_bounds__(256) void proj_tc_kernel(
    const float* __restrict__ x, const float* __restrict__ y,
    const float* __restrict__ wqx, const float* __restrict__ bqx,
    const float* __restrict__ wkx, const float* __restrict__ bkx,
    const float* __restrict__ wvx, const float* __restrict__ bvx,
    const float* __restrict__ wqy, const float* __restrict__ bqy,
    const float* __restrict__ wky, const float* __restrict__ bky,
    const float* __restrict__ wvy, const float* __restrict__ bvy)
{
    const int inp = blockIdx.z >> 3;
    const int b   = blockIdx.z & 7;
    const int n0  = blockIdx.x * 64;
    const int O0  = blockIdx.y * 64;

    const float* in = inp ? y : x;
    const float* wq = inp ? wqy : wqx;  const float* bq = inp ? bqy : bqx;
    const float* wk = inp ? wky : wkx;  const float* bk = inp ? bky : bkx;
    const float* wv = inp ? wvy : wvx;  const float* bv = inp ? bvy : bvx;
    const int qb = inp ? 0 : 1;     // x-proj feeds branch1 Q/K, y-proj branch0
    const int vb = inp ? 1 : 0;     // x-proj v -> branch0 V, y-proj v -> branch1

    // smem: phase1 Wh/Wl [64][40] + Xh/Xl [32][72] bf16 = 19456B
    //       phase2 sT [64][68] fp32 = 17408B (aliased)
    __shared__ __align__(16) char smemraw[19968];
    __nv_bfloat16* sWh = (__nv_bfloat16*)smemraw;
    __nv_bfloat16* sWl = sWh + 64 * 40;
    __nv_bfloat16* sXh = sWl + 64 * 40;
    __nv_bfloat16* sXl = sXh + 32 * 72;
    float* sT = (float*)smemraw;          // [64][68]

    const int tid = threadIdx.x;
    const int w = tid >> 5, l = tid & 31;
    const int rg = w & 3, ng = w >> 2;
    const int grp = l >> 2, t4 = l & 3;
    const int lrow = l & 15;
    const int hi8 = (l & 16) ? 8 : 0;

    // W load mapping: row = tid>>2 (0..63), cseg = (tid&3)*8
    const int wrow_i = tid >> 2;
    const int wcseg  = (tid & 3) * 8;
    const int og = O0 + wrow_i;
    const float* wrow = (og < 32) ? (wq + (size_t)og * CC)
                      : (og < 64) ? (wk + (size_t)(og - 32) * CC)
                                  : (wv + (size_t)(og - 64) * CC);
    // X load mapping: row = tid>>3 (0..31), nseg = (tid&7)*8
    const int xrow_i = tid >> 3;
    const int xnseg  = (tid & 7) * 8;
    const float* xbase = in + ((size_t)b * CC + xrow_i) * NN + n0 + xnseg;

    float acc[4][4];
    #pragma unroll
    for (int t = 0; t < 4; t++)
        #pragma unroll
        for (int i = 0; i < 4; i++) acc[t][i] = 0.f;

    for (int c0 = 0; c0 < CC; c0 += 32) {
        // stage W chunk [64 o][32 c] and X chunk [32 c][64 n], split hi/lo
        {
            float4 wa = *(const float4*)(wrow + c0 + wcseg);
            float4 wb = *(const float4*)(wrow + c0 + wcseg + 4);
            float v[8] = {wa.x, wa.y, wa.z, wa.w, wb.x, wb.y, wb.z, wb.w};
            split_store8(v, &sWh[wrow_i * 40 + wcseg], &sWl[wrow_i * 40 + wcseg]);
        }
        {
            const float* xp = xbase + (size_t)c0 * NN;
            float4 xa = *(const float4*)xp;
            float4 xc = *(const float4*)(xp + 4);
            float v[8] = {xa.x, xa.y, xa.z, xa.w, xc.x, xc.y, xc.z, xc.w};
            split_store8(v, &sXh[xrow_i * 72 + xnseg], &sXl[xrow_i * 72 + xnseg]);
        }
        __syncthreads();

        #pragma unroll
        for (int kc = 0; kc < 2; kc++) {
            u32 ah[4], al[4];
            ldsm4(ah, s2u(&sWh[(rg * 16 + lrow) * 40 + kc * 16 + hi8]));
            ldsm4(al, s2u(&sWl[(rg * 16 + lrow) * 40 + kc * 16 + hi8]));
            #pragma unroll
            for (int sp = 0; sp < 2; sp++) {
                u32 bh[4], bl[4];
                int xoff = (kc * 16 + lrow) * 72 + ng * 32 + sp * 16 + hi8;
                ldsm4t(bh, s2u(&sXh[xoff]));
                ldsm4t(bl, s2u(&sXl[xoff]));
                int t = sp * 2;
                mma_bf16(acc[t], ah, bh[0], bh[1]);
                mma_bf16(acc[t], ah, bl[0], bl[1]);
                mma_bf16(acc[t], al, bh[0], bh[1]);
                mma_bf16(acc[t+1], ah, bh[2], bh[3]);
                mma_bf16(acc[t+1], ah, bl[2], bl[3]);
                mma_bf16(acc[t+1], al, bh[2], bh[3]);
            }
        }
        __syncthreads();
    }

    // bias for this thread's two o rows
    const int ol0 = rg * 16 + grp, ol1 = ol0 + 8;
    float bias0, bias1;
    {
        int o0g = O0 + ol0, o1g = O0 + ol1;
        bias0 = (o0g < 32) ? bq[o0g] : (o0g < 64) ? bk[o0g - 32] : bv[o0g - 64];
        bias1 = (o1g < 32) ? bq[o1g] : (o1g < 64) ? bk[o1g - 32] : bv[o1g - 64];
    }

    // transpose via smem: sT[n_local][o_local]
    #pragma unroll
    for (int t = 0; t < 4; t++) {
        int nl = ng * 32 + (t >> 1) * 16 + (t & 1) * 8 + 2 * t4;
        sT[nl * 68 + ol0]       = acc[t][0] + bias0;
        sT[(nl + 1) * 68 + ol0] = acc[t][1] + bias0;
        sT[nl * 68 + ol1]       = acc[t][2] + bias1;
        sT[(nl + 1) * 68 + ol1] = acc[t][3] + bias1;
    }
    __syncthreads();

    // coalesced store-out: 4 threads per n row, 16 outputs each
    {
        int row  = tid >> 2;
        int oseg = (tid & 3) * 16;
        int n = n0 + row;
        float4 v0 = *(const float4*)&sT[row * 68 + oseg];
        float4 v1 = *(const float4*)&sT[row * 68 + oseg + 4];
        float4 v2 = *(const float4*)&sT[row * 68 + oseg + 8];
        float4 v3 = *(const float4*)&sT[row * 68 + oseg + 12];
        float vv[16] = {v0.x,v0.y,v0.z,v0.w, v1.x,v1.y,v1.z,v1.w,
                        v2.x,v2.y,v2.z,v2.w, v3.x,v3.y,v3.z,v3.w};
        if (O0 == 0) {
            u32 hw[8], lw[8];
            #pragma unroll
            for (int i = 0; i < 8; i++) {
                float a = vv[2*i], c = vv[2*i+1];
                __nv_bfloat16 ha = __float2bfloat16(a), hc = __float2bfloat16(c);
                hw[i] = cvt_bf16x2(__bfloat162float(hc), __bfloat162float(ha));
                lw[i] = cvt_bf16x2(c - __bfloat162float(hc), a - __bfloat162float(ha));
            }
            if (oseg < 32) {
                *(uint4*)&g_qh[qb][b][n][oseg]     = make_uint4(hw[0],hw[1],hw[2],hw[3]);
                *(uint4*)&g_qh[qb][b][n][oseg + 8] = make_uint4(hw[4],hw[5],hw[6],hw[7]);
                *(uint4*)&g_ql[qb][b][n][oseg]     = make_uint4(lw[0],lw[1],lw[2],lw[3]);
                *(uint4*)&g_ql[qb][b][n][oseg + 8] = make_uint4(lw[4],lw[5],lw[6],lw[7]);
            } else {
                int ko = oseg - 32;
                *(uint4*)&g_kh[qb][b][n][ko]     = make_uint4(hw[0],hw[1],hw[2],hw[3]);
                *(uint4*)&g_kh[qb][b][n][ko + 8] = make_uint4(hw[4],hw[5],hw[6],hw[7]);
                *(uint4*)&g_kl[qb][b][n][ko]     = make_uint4(lw[0],lw[1],lw[2],lw[3]);
                *(uint4*)&g_kl[qb][b][n][ko + 8] = make_uint4(lw[4],lw[5],lw[6],lw[7]);
            }
        } else {
            int cb = O0 - 64 + oseg;
            u32 hw[8];
            #pragma unroll
            for (int i = 0; i < 8; i++)
                hw[i] = cvt_bf16x2(vv[2*i+1], vv[2*i]);
            *(uint4*)&g_vb[vb][b][n][cb]     = make_uint4(hw[0],hw[1],hw[2],hw[3]);
            *(uint4*)&g_vb[vb][b][n][cb + 8] = make_uint4(hw[4],hw[5],hw[6],hw[7]);
        }
    }
}

// ---------------------------------------------------------------------------
// Tensor-core fused attention, register-resident P, cp.async double-buffered.
// Block: 64 queries, 8 warps. Warp w: rg = w&3 (16 query rows), ch = w>>2
// (PV channel half). No-max softmax (logits bounded ~35, safe in fp32).
// ---------------------------------------------------------------------------
__global__ __launch_bounds__(256, 2) void attn_kernel(
    const float* __restrict__ x, const float* __restrict__ y,
    const float* __restrict__ gx, const float* __restrict__ gy,
    float* __restrict__ out)
{
    const int br  = blockIdx.z;
    const int b   = blockIdx.y;
    const int i0  = blockIdx.x * 64;
    const int tid = threadIdx.x;
    const int w   = tid >> 5;
    const int l   = tid & 31;
    const int rg  = w & 3;
    const int ch  = w >> 2;
    const int grp = l >> 2;
    const int t4  = l & 3;
    const int q0  = rg * 16;

    const float* res = br ? y : x;
    const float* gmm = br ? gy : gx;
    float* outp = out + (size_t)br * BB * CC * NN;

    extern __shared__ __align__(16) __nv_bfloat16 smem[];
    __nv_bfloat16* sKh = smem;                    // 2*1280
    __nv_bfloat16* sKl = sKh + 2 * 32 * 40;       // 2*1280
    __nv_bfloat16* sV  = sKl + 2 * 32 * 40;       // 2*8448
    __nv_bfloat16* sQh = sV  + 2 * 32 * 264;      // 2560
    __nv_bfloat16* sQl = sQh + 64 * 40;           // 2560

    {
        int row = tid >> 2, c8 = (tid & 3) * 8;
        *(float4*)&sQh[row * 40 + c8] = *(const float4*)&g_qh[br][b][i0 + row][c8];
        *(float4*)&sQl[row * 40 + c8] = *(const float4*)&g_ql[br][b][i0 + row][c8];
    }
    __syncthreads();

    u32 qh[2][4], ql[2][4];
    {
        int row = q0 + (l & 15);
        int cofs = (l & 16) ? 8 : 0;
        #pragma unroll
        for (int kc = 0; kc < 2; kc++) {
            ldsm4(qh[kc], s2u(&sQh[row * 40 + kc * 16 + cofs]));
            ldsm4(ql[kc], s2u(&sQl[row * 40 + kc * 16 + cofs]));
        }
    }

    const __nv_bfloat16* khg = &g_kh[br][b][0][0];
    const __nv_bfloat16* klg = &g_kl[br][b][0][0];
    const __nv_bfloat16* vg  = &g_vb[br][b][0][0];

    const int krow = (tid & 127) >> 2;
    const int kc8  = ((tid & 127) & 3) * 8;
    const bool khi = tid < 128;

    float acc[16][4];
    #pragma unroll
    for (int t = 0; t < 16; t++)
        #pragma unroll
        for (int i = 0; i < 4; i++) acc[t][i] = 0.f;
    float lsA = 0.f, lsB = 0.f;

    {
        __nv_bfloat16* dK = khi ? sKh : sKl;
        const __nv_bfloat16* gK = khi ? khg : klg;
        cpasync16(s2u(&dK[krow * 40 + kc8]), gK + (size_t)krow * 32 + kc8);
        #pragma unroll
        for (int it = 0; it < 4; it++) {
            int idx = tid + it * 256;
            int vr = idx >> 5, vc8 = (idx & 31) * 8;
            cpasync16(s2u(&sV[vr * 264 + vc8]), vg + (size_t)vr * CC + vc8);
        }
        cpcommit();
    }

    const int ldA = (l & 16) ? 8 : 0;
    const int krA = ((l >> 4) << 3) + (l & 7);
    const int kcA = ((l >> 3) & 1) * 8;

    for (int jt = 0; jt < NT; jt++) {
        const int buf = jt & 1;
        if (jt + 1 < NT) {
            const int nb = buf ^ 1;
            const size_t j1 = (size_t)(jt + 1) * 32;
            __nv_bfloat16* dK = (khi ? sKh : sKl) + nb * 32 * 40;
            const __nv_bfloat16* gK = khi ? khg : klg;
            cpasync16(s2u(&dK[krow * 40 + kc8]), gK + (j1 + krow) * 32 + kc8);
            __nv_bfloat16* dV = sV + nb * 32 * 264;
            #pragma unroll
            for (int it = 0; it < 4; it++) {
                int idx = tid + it * 256;
                int vr = idx >> 5, vc8 = (idx & 31) * 8;
                cpasync16(s2u(&dV[vr * 264 + vc8]), vg + (j1 + vr) * CC + vc8);
            }
            cpcommit();
            cpwait1();
        } else {
            cpwait0();
        }
        __syncthreads();

        const __nv_bfloat16* bKh = sKh + buf * 32 * 40;
        const __nv_bfloat16* bKl = sKl + buf * 32 * 40;
        const __nv_bfloat16* bV  = sV  + buf * 32 * 264;

        float sc[4][4];
        #pragma unroll
        for (int t = 0; t < 4; t++)
            #pragma unroll
            for (int i = 0; i < 4; i++) sc[t][i] = 0.f;

        #pragma unroll
        for (int jg = 0; jg < 2; jg++) {
            #pragma unroll
            for (int kc = 0; kc < 2; kc++) {
                u32 kh4[4], kl4[4];
                ldsm4(kh4, s2u(&bKh[(jg * 16 + krA) * 40 + kc * 16 + kcA]));
                ldsm4(kl4, s2u(&bKl[(jg * 16 + krA) * 40 + kc * 16 + kcA]));
                mma_bf16(sc[jg * 2],     qh[kc], kh4[0], kh4[1]);
                mma_bf16(sc[jg * 2],     qh[kc], kl4[0], kl4[1]);
                mma_bf16(sc[jg * 2],     ql[kc], kh4[0], kh4[1]);
                mma_bf16(sc[jg * 2 + 1], qh[kc], kh4[2], kh4[3]);
                mma_bf16(sc[jg * 2 + 1], qh[kc], kl4[2], kl4[3]);
                mma_bf16(sc[jg * 2 + 1], ql[kc], kh4[2], kh4[3]);
            }
        }

        u32 pa[2][4];
        #pragma unroll
        for (int t = 0; t < 4; t++) {
            float e0 = __expf(sc[t][0]);
            float e1 = __expf(sc[t][1]);
            float e2 = __expf(sc[t][2]);
            float e3 = __expf(sc[t][3]);
            lsA += e0 + e1;
            lsB += e2 + e3;
            int kj = t >> 1, sub = (t & 1) * 2;
            pa[kj][sub]     = cvt_bf16x2(e1, e0);
            pa[kj][sub + 1] = cvt_bf16x2(e3, e2);
        }

        #pragma unroll
        for (int g = 0; g < 8; g++) {
            int n0 = ch * 128 + g * 16 + ldA;
            #pragma unroll
            for (int kj = 0; kj < 2; kj++) {
                u32 vb4[4];
                ldsm4t(vb4, s2u(&bV[(kj * 16 + (l & 15)) * 264 + n0]));
                mma_bf16(acc[g * 2],     pa[kj], vb4[0], vb4[1]);
                mma_bf16(acc[g * 2 + 1], pa[kj], vb4[2], vb4[3]);
            }
        }
        __syncthreads();
    }

    lsA += __shfl_xor_sync(0xffffffffu, lsA, 1);
    lsA += __shfl_xor_sync(0xffffffffu, lsA, 2);
    lsB += __shfl_xor_sync(0xffffffffu, lsB, 1);
    lsB += __shfl_xor_sync(0xffffffffu, lsB, 2);

    const float g = gmm[0];
    float rl0 = g / lsA, rl1 = g / lsB;
    int ir0 = i0 + q0 + grp;
    int ir1 = ir0 + 8;
    #pragma unroll
    for (int t = 0; t < 16; t++) {
        int c0 = ch * 128 + t * 8 + 2 * t4;
        size_t base = ((size_t)b * CC + c0) * NN;
        outp[base + ir0]      = acc[t][0] * rl0 + res[base + ir0];
        outp[base + NN + ir0] = acc[t][1] * rl0 + res[base + NN + ir0];
        outp[base + ir1]      = acc[t][2] * rl1 + res[base + ir1];
        outp[base + NN + ir1] = acc[t][3] * rl1 + res[base + NN + ir1];
    }
}

// ---------------------------------------------------------------------------

extern "C" void kernel_launch(void* const* d_in, const int* in_sizes, int n_in,
                              void* d_out, int out_size)
{
    const float* x   = (const float*)d_in[0];
    const float* y   = (const float*)d_in[1];
    const float* wqx = (const float*)d_in[2];
    const float* bqx = (const float*)d_in[3];
    const float* wkx = (const float*)d_in[4];
    const float* bkx = (const float*)d_in[5];
    const float* wvx = (const float*)d_in[6];
    const float* bvx = (const float*)d_in[7];
    const float* wqy = (const float*)d_in[8];
    const float* bqy = (const float*)d_in[9];
    const float* wky = (const float*)d_in[10];
    const float* bky = (const float*)d_in[11];
    const float* wvy = (const float*)d_in[12];
    const float* bvy = (const float*)d_in[13];
    const float* gx  = (const float*)d_in[14];
    const float* gy  = (const float*)d_in[15];
    float* out = (float*)d_out;

    const int ATTN_SMEM = (2*1280 + 2*1280 + 2*8448 + 2560 + 2560) * 2;
    cudaFuncSetAttribute(attn_kernel, cudaFuncAttributeMaxDynamicSharedMemorySize, ATTN_SMEM);

    dim3 pgrid(NN / 64, 320 / 64, 2 * BB);
    proj_tc_kernel<<<pgrid, 256>>>(x, y, wqx, bqx, wkx, bkx, wvx, bvx,
                                   wqy, bqy, wky, bky, wvy, bvy);

    dim3 agrid(NN / 64, BB, 2);
    attn_kernel<<<agrid, 256, ATTN_SMEM>>>(x, y, gx, gy, out);
}